// round 1
// baseline (speedup 1.0000x reference)
#include <cuda_runtime.h>

#define Cc   256
#define Bn   8
#define Hh   128
#define Ww   128
#define NWw  512
#define HW   (Hh*Ww)
#define EPSf 1e-5f

typedef unsigned long long ull;

__device__ float g_scale[Cc];
__device__ float g_shift[Cc];
__device__ float g_w1t[NWw * Cc];   // transposed w1: [j][c]

// ---------------------------------------------------------------------------
// Kernel 1: per-channel batch stats -> folded scale/shift
// ---------------------------------------------------------------------------
__global__ void stats_kernel(const float* __restrict__ x,
                             const float* __restrict__ gamma,
                             const float* __restrict__ beta) {
    int c = blockIdx.x;
    int tid = threadIdx.x;
    float s = 0.f, s2 = 0.f;
    for (int b = 0; b < Bn; b++) {
        const float* p = x + (size_t)(b * Cc + c) * HW;
        for (int i = tid; i < HW; i += 256) {
            float v = __ldg(p + i);
            s += v;
            s2 += v * v;
        }
    }
    __shared__ float sh[256], sh2[256];
    sh[tid] = s;
    sh2[tid] = s2;
    __syncthreads();
    for (int off = 128; off > 0; off >>= 1) {
        if (tid < off) {
            sh[tid]  += sh[tid + off];
            sh2[tid] += sh2[tid + off];
        }
        __syncthreads();
    }
    if (tid == 0) {
        float n    = (float)(Bn * HW);
        float mean = sh[0] / n;
        float var  = sh2[0] / n - mean * mean;
        float sc   = gamma[c] * rsqrtf(var + EPSf);
        g_scale[c] = sc;
        g_shift[c] = beta[c] - mean * sc;
    }
}

// ---------------------------------------------------------------------------
// Kernel 2: transpose w1 [C][NW] -> [NW][C] for coalesced/vectorized GEMM loads
// ---------------------------------------------------------------------------
__global__ void transpose_w1(const float* __restrict__ w1) {
    int idx = blockIdx.x * 256 + threadIdx.x;   // idx = j*C + c
    int j = idx >> 8;
    int c = idx & 255;
    g_w1t[idx] = w1[c * NWw + j];
}

// ---------------------------------------------------------------------------
// Kernel 3: fused  BN(x) -> depthwise3x3 -> relu -> 1x1 -> +b1 +x
// block: 256 threads, handles 64 pixels of one row (b,h,w0..w0+63), all 256
// output channels. Thread tile: 8 channels x 8 pixels (f32x2 accumulators).
// ---------------------------------------------------------------------------
__global__ __launch_bounds__(256)
void fused_kernel(const float* __restrict__ x,
                  const float* __restrict__ lbp,
                  const float* __restrict__ b1,
                  float* __restrict__ out) {
    // per-chunk smem (chunk = 8 input channels -> 16 depthwise output channels)
    __shared__ float xn_s[8 * 3 * 72];    // [ci][r][col], col 0..65 valid
    __shared__ float y_s[16 * 64];        // [jl][p]
    __shared__ float w1_s[16 * 256];      // [jl][c]
    __shared__ float lbp_s[16 * 9];

    const int tid = threadIdx.x;
    const int tc  = tid >> 3;             // 0..31
    const int tp  = tid & 7;              // 0..7
    const int c0  = tc * 8;
    const int p0  = tp * 8;
    const int w0  = blockIdx.x * 64;
    const int h   = blockIdx.y;
    const int b   = blockIdx.z;

    // accumulators: z[cc*4+k] = packed f32x2 of pixels (p0+2k, p0+2k+1), chan c0+cc
    ull z[32];
    #pragma unroll
    for (int cc = 0; cc < 8; cc++) {
        int c = c0 + cc;
        float bb = __ldg(b1 + c);
        ull bb2;
        asm("mov.b64 %0, {%1, %1};" : "=l"(bb2) : "f"(bb));
        const ull* xr = (const ull*)(x + (size_t)(b * Cc + c) * HW + h * Ww + w0 + p0);
        #pragma unroll
        for (int k = 0; k < 4; k++) {
            ull xv = xr[k];
            asm("add.rn.f32x2 %0, %1, %2;" : "=l"(z[cc * 4 + k]) : "l"(xv), "l"(bb2));
        }
    }

    for (int ch = 0; ch < 32; ch++) {
        const int cbase = ch * 8;
        const int jbase = ch * 16;
        __syncthreads();  // protect smem from previous iteration's readers

        // --- load + normalize x halo tile: 8 chans x 3 rows x 66 cols ---
        for (int idx = tid; idx < 8 * 3 * 66; idx += 256) {
            int ci  = idx / 198;
            int rem = idx - ci * 198;
            int r   = rem / 66;
            int col = rem - r * 66;
            int hh  = h - 1 + r;
            int wg  = w0 - 1 + col;
            float v = 0.f;
            if ((unsigned)hh < (unsigned)Hh && (unsigned)wg < (unsigned)Ww) {
                int c = cbase + ci;
                v = __ldg(x + (size_t)(b * Cc + c) * HW + hh * Ww + wg) * g_scale[c]
                    + g_shift[c];
            }
            xn_s[ci * 216 + r * 72 + col] = v;
        }

        // --- load w1 chunk [16][256] (coalesced float4) ---
        {
            const float4* src = (const float4*)(g_w1t + jbase * Cc);
            float4* dst = (float4*)w1_s;
            #pragma unroll
            for (int k = 0; k < 4; k++)
                dst[tid + k * 256] = src[tid + k * 256];
        }
        if (tid < 144) lbp_s[tid] = __ldg(lbp + jbase * 9 + tid);
        __syncthreads();

        // --- depthwise 3x3 + relu: 16 x 64 values, 4 per thread ---
        #pragma unroll
        for (int k = 0; k < 4; k++) {
            int idx = tid + k * 256;
            int jl  = idx >> 6;
            int p   = idx & 63;
            int ci  = jl >> 1;
            const float* lw  = lbp_s + jl * 9;
            const float* xr0 = xn_s + ci * 216 + p;
            float acc = 0.f;
            #pragma unroll
            for (int r = 0; r < 3; r++) {
                const float* row = xr0 + r * 72;
                acc += lw[r * 3 + 0] * row[0];
                acc += lw[r * 3 + 1] * row[1];
                acc += lw[r * 3 + 2] * row[2];
            }
            y_s[jl * 64 + p] = fmaxf(acc, 0.f);
        }
        __syncthreads();

        // --- register-blocked GEMM accumulate (packed f32x2 FMA) ---
        #pragma unroll
        for (int jl = 0; jl < 16; jl++) {
            const ull* yp = (const ull*)(y_s + jl * 64 + p0);
            ull y0 = yp[0], y1 = yp[1], y2v = yp[2], y3v = yp[3];
            const float4* wp = (const float4*)(w1_s + jl * 256 + c0);
            float4 wa = wp[0], wb = wp[1];
            float wr[8] = {wa.x, wa.y, wa.z, wa.w, wb.x, wb.y, wb.z, wb.w};
            #pragma unroll
            for (int cc = 0; cc < 8; cc++) {
                ull ww;
                asm("mov.b64 %0, {%1, %1};" : "=l"(ww) : "f"(wr[cc]));
                asm("fma.rn.f32x2 %0, %1, %2, %0;" : "+l"(z[cc * 4 + 0]) : "l"(ww), "l"(y0));
                asm("fma.rn.f32x2 %0, %1, %2, %0;" : "+l"(z[cc * 4 + 1]) : "l"(ww), "l"(y1));
                asm("fma.rn.f32x2 %0, %1, %2, %0;" : "+l"(z[cc * 4 + 2]) : "l"(ww), "l"(y2v));
                asm("fma.rn.f32x2 %0, %1, %2, %0;" : "+l"(z[cc * 4 + 3]) : "l"(ww), "l"(y3v));
            }
        }
    }

    // --- store: z already holds (1x1 conv + b1 + x residual) ---
    #pragma unroll
    for (int cc = 0; cc < 8; cc++) {
        ull* op = (ull*)(out + (size_t)(b * Cc + c0 + cc) * HW + h * Ww + w0 + p0);
        #pragma unroll
        for (int k = 0; k < 4; k++)
            op[k] = z[cc * 4 + k];
    }
}

// ---------------------------------------------------------------------------
extern "C" void kernel_launch(void* const* d_in, const int* in_sizes, int n_in,
                              void* d_out, int out_size) {
    const float* x     = (const float*)d_in[0];
    const float* gamma = (const float*)d_in[1];
    const float* beta  = (const float*)d_in[2];
    const float* lbp   = (const float*)d_in[3];
    const float* w1    = (const float*)d_in[4];
    const float* b1    = (const float*)d_in[5];
    float* out = (float*)d_out;

    stats_kernel<<<Cc, 256>>>(x, gamma, beta);
    transpose_w1<<<(NWw * Cc) / 256, 256>>>(w1);
    fused_kernel<<<dim3(2, Hh, Bn), 256>>>(x, lbp, b1, out);
}

// round 3
// speedup vs baseline: 2.9439x; 2.9439x over previous
#include <cuda_runtime.h>
#include <cuda_fp16.h>
#include <cstdint>

#define Cc   256
#define Bn   8
#define Hh   128
#define Ww   128
#define NWw  512
#define HW   (Hh*Ww)
#define NPIX (Bn*HW)          // 131072
#define EPSf 1e-5f

// ---- scratch (__device__ globals; no allocations allowed) -------------------
__device__ float  g_ps [Cc*Bn];
__device__ float  g_ps2[Cc*Bn];
__device__ float  g_scale[Cc];
__device__ float  g_shift[Cc];
__device__ __half g_w1h[Cc*NWw];                 // [c][j] K-major A operand
__device__ __half g_y[(size_t)NPIX * NWw];       // [pixel][j] K-major B operand

__device__ __forceinline__ uint32_t smem_u32(const void* p) {
    uint32_t a;
    asm("{ .reg .u64 t; cvta.to.shared.u64 t, %1; cvt.u32.u64 %0, t; }"
        : "=r"(a) : "l"(p));
    return a;
}

// ---------------------------------------------------------------------------
// Kernel 1: per-(c,b) partial sums (deterministic 2-stage stats), 2048 blocks
// ---------------------------------------------------------------------------
__global__ __launch_bounds__(256) void stats_part(const float* __restrict__ x) {
    int c = blockIdx.x, b = blockIdx.y, tid = threadIdx.x;
    const float4* p = (const float4*)(x + ((size_t)(b * Cc + c)) * HW);
    float s = 0.f, s2 = 0.f;
    #pragma unroll 4
    for (int i = tid; i < HW / 4; i += 256) {
        float4 v = __ldg(p + i);
        s  += v.x + v.y + v.z + v.w;
        s2 += v.x*v.x + v.y*v.y + v.z*v.z + v.w*v.w;
    }
    __shared__ float sh[256], sh2[256];
    sh[tid] = s; sh2[tid] = s2;
    __syncthreads();
    for (int off = 128; off > 0; off >>= 1) {
        if (tid < off) { sh[tid] += sh[tid+off]; sh2[tid] += sh2[tid+off]; }
        __syncthreads();
    }
    if (tid == 0) { g_ps[c*Bn + b] = sh[0]; g_ps2[c*Bn + b] = sh2[0]; }
}

__global__ void finalize_stats(const float* __restrict__ gamma,
                               const float* __restrict__ beta) {
    int c = threadIdx.x;
    float s = 0.f, s2 = 0.f;
    #pragma unroll
    for (int b = 0; b < Bn; b++) { s += g_ps[c*Bn+b]; s2 += g_ps2[c*Bn+b]; }
    float n = (float)(Bn * HW);
    float mean = s / n;
    float var  = s2 / n - mean * mean;
    float sc   = gamma[c] * rsqrtf(var + EPSf);
    g_scale[c] = sc;
    g_shift[c] = beta[c] - mean * sc;
}

__global__ void w1half(const float* __restrict__ w1) {
    int i = blockIdx.x * 256 + threadIdx.x;
    g_w1h[i] = __float2half_rn(w1[i]);
}

// ---------------------------------------------------------------------------
// Kernel 2: BN -> depthwise 3x3 -> relu -> fp16 y[pixel][j]
// ---------------------------------------------------------------------------
__global__ __launch_bounds__(256)
void dw_kernel(const float* __restrict__ x, const float* __restrict__ lbp) {
    __shared__ float xs[8][3][136];
    __shared__ float lw[16][9];

    const int tid = threadIdx.x;
    const int h = blockIdx.x, b = blockIdx.y;
    const int p  = tid & 127;
    const int jh = tid >> 7;                    // 0..1
    const size_t pixrow = ((size_t)b * Hh + h) * Ww;

    for (int ch = 0; ch < 32; ch++) {
        const int cbase = ch * 8, jbase = ch * 16;
        __syncthreads();
        for (int idx = tid; idx < 8 * 3 * 130; idx += 256) {
            int ci  = idx / 390;
            int rem = idx - ci * 390;
            int r   = rem / 130;
            int col = rem - r * 130;
            int hh  = h - 1 + r;
            int wg  = col - 1;
            float v = 0.f;
            if ((unsigned)hh < (unsigned)Hh && (unsigned)wg < (unsigned)Ww) {
                int c = cbase + ci;
                v = __ldg(x + ((size_t)(b * Cc + c)) * HW + hh * Ww + wg)
                    * g_scale[c] + g_shift[c];
            }
            xs[ci][r][col] = v;
        }
        if (tid < 144) ((float*)lw)[tid] = __ldg(lbp + jbase * 9 + tid);
        __syncthreads();

        __align__(16) __half o8[8];
        #pragma unroll
        for (int q = 0; q < 8; q++) {
            int jl = jh * 8 + q;
            int ci = jl >> 1;
            const float* wv = lw[jl];
            float acc = 0.f;
            #pragma unroll
            for (int r = 0; r < 3; r++) {
                acc = fmaf(wv[r*3+0], xs[ci][r][p+0], acc);
                acc = fmaf(wv[r*3+1], xs[ci][r][p+1], acc);
                acc = fmaf(wv[r*3+2], xs[ci][r][p+2], acc);
            }
            o8[q] = __float2half_rn(fmaxf(acc, 0.f));
        }
        *(uint4*)(g_y + (pixrow + p) * NWw + jbase + jh * 8) = *(const uint4*)o8;
    }
}

// ---------------------------------------------------------------------------
// Kernel 3: HMMA (mma.sync m16n8k16) GEMM
//   out[c][pix] = sum_j w1[c][j]*y[pix][j] + b1[c] + x[c][pix]
// Block tile: 128 (M=channels) x 128 (N=pixels), K=512 in 8 chunks of 64.
// 8 warps (2x4), warp tile 64x32.
// ---------------------------------------------------------------------------
__global__ __launch_bounds__(256)
void gemm_kernel(const float* __restrict__ x, const float* __restrict__ b1,
                 float* __restrict__ out) {
    // single-stage tiles, XOR-swizzled 16B units: 128 rows x 128B each
    __shared__ __align__(1024) char sAb[128 * 128];
    __shared__ __align__(1024) char sBb[128 * 128];
    const uint32_t sA = smem_u32(sAb);
    const uint32_t sB = smem_u32(sBb);

    const int tid  = threadIdx.x;
    const int wid  = tid >> 5, lane = tid & 31;
    const int wm   = wid & 1;          // 2 warps along M
    const int wn   = wid >> 1;         // 4 warps along N
    const int mt   = blockIdx.x;       // 0..1, channel base mt*128
    const size_t p0 = (size_t)blockIdx.y * 128;   // pixel base

    float acc[4][4][4];
    #pragma unroll
    for (int mi = 0; mi < 4; mi++)
        #pragma unroll
        for (int ni = 0; ni < 4; ni++)
            #pragma unroll
            for (int q = 0; q < 4; q++) acc[mi][ni][q] = 0.f;

    const __half* wsrc = g_w1h + (size_t)mt * 128 * NWw;

    for (int kc = 0; kc < 8; kc++) {
        const int k0 = kc * 64;
        // fill A and B tiles: 128 rows x 8 units of 16B each, cp.async
        #pragma unroll
        for (int i = 0; i < 4; i++) {
            int idx = tid + i * 256;
            int row = idx >> 3, u = idx & 7;
            const __half* srcA = wsrc + (size_t)row * NWw + k0 + u * 8;
            uint32_t dA = sA + row * 128 + ((u ^ (row & 7)) << 4);
            asm volatile("cp.async.cg.shared.global [%0], [%1], 16;"
                         :: "r"(dA), "l"(srcA));
            const __half* srcB = g_y + (p0 + row) * NWw + k0 + u * 8;
            uint32_t dB = sB + row * 128 + ((u ^ (row & 7)) << 4);
            asm volatile("cp.async.cg.shared.global [%0], [%1], 16;"
                         :: "r"(dB), "l"(srcB));
        }
        asm volatile("cp.async.commit_group;");
        asm volatile("cp.async.wait_group 0;");
        __syncthreads();

        #pragma unroll
        for (int ks = 0; ks < 4; ks++) {
            uint32_t a[4][4], bf[4][2];
            #pragma unroll
            for (int mi = 0; mi < 4; mi++) {
                int row = wm * 64 + mi * 16 + (lane & 15);
                int u   = ks * 2 + (lane >> 4);
                uint32_t ad = sA + row * 128 + ((u ^ (row & 7)) << 4);
                asm volatile(
                    "ldmatrix.sync.aligned.m8n8.x4.shared.b16 {%0,%1,%2,%3}, [%4];"
                    : "=r"(a[mi][0]), "=r"(a[mi][1]), "=r"(a[mi][2]), "=r"(a[mi][3])
                    : "r"(ad));
            }
            #pragma unroll
            for (int ni = 0; ni < 4; ni++) {
                int row = wn * 32 + ni * 8 + (lane & 7);
                int u   = ks * 2 + ((lane >> 3) & 1);
                uint32_t bd = sB + row * 128 + ((u ^ (row & 7)) << 4);
                asm volatile(
                    "ldmatrix.sync.aligned.m8n8.x2.shared.b16 {%0,%1}, [%2];"
                    : "=r"(bf[ni][0]), "=r"(bf[ni][1]) : "r"(bd));
            }
            #pragma unroll
            for (int mi = 0; mi < 4; mi++)
                #pragma unroll
                for (int ni = 0; ni < 4; ni++)
                    asm volatile(
                        "mma.sync.aligned.m16n8k16.row.col.f32.f16.f16.f32 "
                        "{%0,%1,%2,%3}, {%4,%5,%6,%7}, {%8,%9}, {%0,%1,%2,%3};"
                        : "+f"(acc[mi][ni][0]), "+f"(acc[mi][ni][1]),
                          "+f"(acc[mi][ni][2]), "+f"(acc[mi][ni][3])
                        : "r"(a[mi][0]), "r"(a[mi][1]), "r"(a[mi][2]), "r"(a[mi][3]),
                          "r"(bf[ni][0]), "r"(bf[ni][1]));
        }
        __syncthreads();
    }

    // epilogue: + b1[c] + x residual, float2 stores
    const int bb  = (int)(p0 >> 14);                    // image index
    const int hw0 = (int)(p0 & 16383) + wn * 32 + (lane & 3) * 2;
    #pragma unroll
    for (int mi = 0; mi < 4; mi++) {
        int cb = mt * 128 + wm * 64 + mi * 16 + (lane >> 2);
        #pragma unroll
        for (int h = 0; h < 2; h++) {
            int c = cb + h * 8;
            float bias = __ldg(b1 + c);
            size_t base = ((size_t)(bb * Cc + c)) * HW + hw0;
            #pragma unroll
            for (int ni = 0; ni < 4; ni++) {
                size_t o = base + ni * 8;
                float2 xv = *(const float2*)(x + o);
                float2 r;
                r.x = acc[mi][ni][h * 2 + 0] + bias + xv.x;
                r.y = acc[mi][ni][h * 2 + 1] + bias + xv.y;
                *(float2*)(out + o) = r;
            }
        }
    }
}

// ---------------------------------------------------------------------------
extern "C" void kernel_launch(void* const* d_in, const int* in_sizes, int n_in,
                              void* d_out, int out_size) {
    const float* x     = (const float*)d_in[0];
    const float* gamma = (const float*)d_in[1];
    const float* beta  = (const float*)d_in[2];
    const float* lbp   = (const float*)d_in[3];
    const float* w1    = (const float*)d_in[4];
    const float* b1    = (const float*)d_in[5];
    float* out = (float*)d_out;

    stats_part<<<dim3(Cc, Bn), 256>>>(x);
    finalize_stats<<<1, Cc>>>(gamma, beta);
    w1half<<<(Cc * NWw) / 256, 256>>>(w1);
    dw_kernel<<<dim3(Hh, Bn), 256>>>(x, lbp);
    gemm_kernel<<<dim3(2, NPIX / 128), 256>>>(x, b1, out);
}

// round 4
// speedup vs baseline: 5.2476x; 1.7825x over previous
#include <cuda_runtime.h>
#include <cuda_fp16.h>
#include <cstdint>

#define Cc   256
#define Bn   8
#define Hh   128
#define Ww   128
#define NWw  512
#define HW   (Hh*Ww)
#define NPIX (Bn*HW)          // 131072
#define EPSf 1e-5f

// ---- scratch (__device__ globals; no allocations allowed) -------------------
__device__ float  g_ps [Cc*Bn];
__device__ float  g_ps2[Cc*Bn];
__device__ float  g_scale[Cc];
__device__ float  g_shift[Cc];
__device__ __half g_w1h[Cc*NWw];                 // [c][j] K-major A operand
__device__ __half g_y[(size_t)NPIX * NWw];       // [pixel][j] K-major B operand

__device__ __forceinline__ uint32_t smem_u32(const void* p) {
    uint32_t a;
    asm("{ .reg .u64 t; cvta.to.shared.u64 t, %1; cvt.u32.u64 %0, t; }"
        : "=r"(a) : "l"(p));
    return a;
}

// ---------------------------------------------------------------------------
// Kernel 1: per-(c,b) partial sums (deterministic 2-stage stats)
// ---------------------------------------------------------------------------
__global__ __launch_bounds__(256) void stats_part(const float* __restrict__ x) {
    int c = blockIdx.x, b = blockIdx.y, tid = threadIdx.x;
    const float4* p = (const float4*)(x + ((size_t)(b * Cc + c)) * HW);
    float s = 0.f, s2 = 0.f;
    #pragma unroll 4
    for (int i = tid; i < HW / 4; i += 256) {
        float4 v = __ldg(p + i);
        s  += v.x + v.y + v.z + v.w;
        s2 += v.x*v.x + v.y*v.y + v.z*v.z + v.w*v.w;
    }
    __shared__ float sh[256], sh2[256];
    sh[tid] = s; sh2[tid] = s2;
    __syncthreads();
    for (int off = 128; off > 0; off >>= 1) {
        if (tid < off) { sh[tid] += sh[tid+off]; sh2[tid] += sh2[tid+off]; }
        __syncthreads();
    }
    if (tid == 0) { g_ps[c*Bn + b] = sh[0]; g_ps2[c*Bn + b] = sh2[0]; }
}

__global__ void finalize_stats(const float* __restrict__ gamma,
                               const float* __restrict__ beta) {
    int c = threadIdx.x;
    float s = 0.f, s2 = 0.f;
    #pragma unroll
    for (int b = 0; b < Bn; b++) { s += g_ps[c*Bn+b]; s2 += g_ps2[c*Bn+b]; }
    float n = (float)(Bn * HW);
    float mean = s / n;
    float var  = s2 / n - mean * mean;
    float sc   = gamma[c] * rsqrtf(var + EPSf);
    g_scale[c] = sc;
    g_shift[c] = beta[c] - mean * sc;
}

__global__ void w1half(const float* __restrict__ w1) {
    int i = blockIdx.x * 256 + threadIdx.x;
    g_w1h[i] = __float2half_rn(w1[i]);
}

// ---------------------------------------------------------------------------
// Kernel 2 (v2): BN -> depthwise 3x3 -> relu -> fp16 y[pixel][j]
// Block: chunk of 8 input channels (16 j), 8-row strip, 128 cols.
// Smem loaded ONCE per block; register-rotating 3x3 stencil down the rows.
// ---------------------------------------------------------------------------
__global__ __launch_bounds__(256)
void dw_kernel(const float* __restrict__ x, const float* __restrict__ lbp) {
    // data for col c lives at [4+c]; taps span [3 .. 132]; [3],[132] zeroed.
    __shared__ float xs[8][10][136];          // 42.5 KB
    __shared__ float lw[16][9];

    const int tid   = threadIdx.x;
    const int chunk = blockIdx.x;             // 0..31
    const int h0    = blockIdx.y * 8;         // row strip
    const int b     = blockIdx.z;
    const int cbase = chunk * 8;
    const int jbase = chunk * 16;

    // zero padding columns
    if (tid < 80) {
        int ci = tid / 10, rr = tid - ci * 10;
        xs[ci][rr][3]   = 0.f;
        xs[ci][rr][132] = 0.f;
    }
    if (tid < 144) ((float*)lw)[tid] = __ldg(lbp + jbase * 9 + tid);

    // main tile: 8 ch x 10 rows x 32 float4, normalized (OOB rows -> 0)
    #pragma unroll
    for (int ci = 0; ci < 8; ci++) {
        const float sc = g_scale[cbase + ci];
        const float sf = g_shift[cbase + ci];
        const float4* src =
            (const float4*)(x + ((size_t)(b * Cc + cbase + ci)) * HW);
        #pragma unroll
        for (int i = 0; i < 2; i++) {
            int idx = tid + i * 256;
            if (idx < 320) {
                int rr = idx >> 5, q = idx & 31;
                int hh = h0 - 1 + rr;
                float4 w = make_float4(0.f, 0.f, 0.f, 0.f);
                if ((unsigned)hh < (unsigned)Hh) {
                    float4 v = __ldg(src + hh * 32 + q);
                    w.x = fmaf(v.x, sc, sf);
                    w.y = fmaf(v.y, sc, sf);
                    w.z = fmaf(v.z, sc, sf);
                    w.w = fmaf(v.w, sc, sf);
                }
                *(float4*)&xs[ci][rr][4 + 4 * q] = w;
            }
        }
    }
    __syncthreads();

    const int p  = tid & 127;                 // column
    const int jh = tid >> 7;                  // 0: j 0..7, 1: j 8..15

    uint32_t opack[8][4];                     // [row][ci] packed half2 (j pair)

    #pragma unroll
    for (int cidx = 0; cidx < 4; cidx++) {
        const int ci = jh * 4 + cidx;
        const int jl = ci * 2;
        float w0[9], w1w[9];
        #pragma unroll
        for (int t = 0; t < 9; t++) { w0[t] = lw[jl][t]; w1w[t] = lw[jl + 1][t]; }

        float a0 = xs[ci][0][3 + p], a1 = xs[ci][0][4 + p], a2 = xs[ci][0][5 + p];
        float b0 = xs[ci][1][3 + p], b1v = xs[ci][1][4 + p], b2 = xs[ci][1][5 + p];
        #pragma unroll
        for (int r = 0; r < 8; r++) {
            float c0 = xs[ci][r + 2][3 + p];
            float c1 = xs[ci][r + 2][4 + p];
            float c2 = xs[ci][r + 2][5 + p];
            float s0, s1;
            s0 = w0[0]*a0;            s1 = w1w[0]*a0;
            s0 = fmaf(w0[1],a1,s0);   s1 = fmaf(w1w[1],a1,s1);
            s0 = fmaf(w0[2],a2,s0);   s1 = fmaf(w1w[2],a2,s1);
            s0 = fmaf(w0[3],b0,s0);   s1 = fmaf(w1w[3],b0,s1);
            s0 = fmaf(w0[4],b1v,s0);  s1 = fmaf(w1w[4],b1v,s1);
            s0 = fmaf(w0[5],b2,s0);   s1 = fmaf(w1w[5],b2,s1);
            s0 = fmaf(w0[6],c0,s0);   s1 = fmaf(w1w[6],c0,s1);
            s0 = fmaf(w0[7],c1,s0);   s1 = fmaf(w1w[7],c1,s1);
            s0 = fmaf(w0[8],c2,s0);   s1 = fmaf(w1w[8],c2,s1);
            __half2 hp = __floats2half2_rn(fmaxf(s0, 0.f), fmaxf(s1, 0.f));
            opack[r][cidx] = *(uint32_t*)&hp;
            a0 = b0; a1 = b1v; a2 = b2;
            b0 = c0; b1v = c1; b2 = c2;
        }
    }

    __half* yb = g_y + ((size_t)(b * Hh + h0) * Ww + p) * NWw + jbase + jh * 8;
    #pragma unroll
    for (int r = 0; r < 8; r++) {
        uint4 v = make_uint4(opack[r][0], opack[r][1], opack[r][2], opack[r][3]);
        *(uint4*)(yb + (size_t)r * Ww * NWw) = v;
    }
}

// ---------------------------------------------------------------------------
// Kernel 3: HMMA GEMM with 2-stage cp.async double-buffer
//   out[c][pix] = sum_j w1[c][j]*y[pix][j] + b1[c] + x[c][pix]
// Block tile 128(M) x 128(N), K=512 in 8 chunks of 64. 8 warps (2x4), 64x32.
// ---------------------------------------------------------------------------
#define STG_BYTES 32768   // per stage: A 16KB + B 16KB

__global__ __launch_bounds__(256)
void gemm_kernel(const float* __restrict__ x, const float* __restrict__ b1,
                 float* __restrict__ out) {
    extern __shared__ __align__(1024) char dsm[];
    const uint32_t s0 = smem_u32(dsm);

    const int tid  = threadIdx.x;
    const int wid  = tid >> 5, lane = tid & 31;
    const int wm   = wid & 1;
    const int wn   = wid >> 1;
    const int mt   = blockIdx.x;
    const size_t p0 = (size_t)blockIdx.y * 128;

    float acc[4][4][4];
    #pragma unroll
    for (int mi = 0; mi < 4; mi++)
        #pragma unroll
        for (int ni = 0; ni < 4; ni++)
            #pragma unroll
            for (int q = 0; q < 4; q++) acc[mi][ni][q] = 0.f;

    const __half* wsrc = g_w1h + (size_t)mt * 128 * NWw;

    const int lrow = tid >> 3, lu = tid & 7;   // fill coords (row += 32/iter)

    // fill stage st with K-chunk kc
    auto fill = [&](int st, int kc) {
        const uint32_t sA = s0 + st * STG_BYTES;
        const uint32_t sB = sA + 16384;
        const int k0 = kc * 64;
        #pragma unroll
        for (int i = 0; i < 4; i++) {
            int row = lrow + i * 32;
            uint32_t sw = ((lu ^ (row & 7)) << 4) + row * 128;
            const __half* srcA = wsrc + (size_t)row * NWw + k0 + lu * 8;
            asm volatile("cp.async.cg.shared.global [%0], [%1], 16;"
                         :: "r"(sA + sw), "l"(srcA));
            const __half* srcB = g_y + (p0 + row) * NWw + k0 + lu * 8;
            asm volatile("cp.async.cg.shared.global [%0], [%1], 16;"
                         :: "r"(sB + sw), "l"(srcB));
        }
        asm volatile("cp.async.commit_group;");
    };

    fill(0, 0);
    for (int kc = 0; kc < 8; kc++) {
        if (kc < 7) fill((kc + 1) & 1, kc + 1);
        if (kc < 7) asm volatile("cp.async.wait_group 1;");
        else        asm volatile("cp.async.wait_group 0;");
        __syncthreads();

        const uint32_t sA = s0 + (kc & 1) * STG_BYTES;
        const uint32_t sB = sA + 16384;

        #pragma unroll
        for (int ks = 0; ks < 4; ks++) {
            uint32_t a[4][4], bf[4][2];
            #pragma unroll
            for (int mi = 0; mi < 4; mi++) {
                int row = wm * 64 + mi * 16 + (lane & 15);
                int u   = ks * 2 + (lane >> 4);
                uint32_t ad = sA + row * 128 + ((u ^ (row & 7)) << 4);
                asm volatile(
                    "ldmatrix.sync.aligned.m8n8.x4.shared.b16 {%0,%1,%2,%3}, [%4];"
                    : "=r"(a[mi][0]), "=r"(a[mi][1]), "=r"(a[mi][2]), "=r"(a[mi][3])
                    : "r"(ad));
            }
            #pragma unroll
            for (int ni = 0; ni < 4; ni++) {
                int row = wn * 32 + ni * 8 + (lane & 7);
                int u   = ks * 2 + ((lane >> 3) & 1);
                uint32_t bd = sB + row * 128 + ((u ^ (row & 7)) << 4);
                asm volatile(
                    "ldmatrix.sync.aligned.m8n8.x2.shared.b16 {%0,%1}, [%2];"
                    : "=r"(bf[ni][0]), "=r"(bf[ni][1]) : "r"(bd));
            }
            #pragma unroll
            for (int mi = 0; mi < 4; mi++)
                #pragma unroll
                for (int ni = 0; ni < 4; ni++)
                    asm volatile(
                        "mma.sync.aligned.m16n8k16.row.col.f32.f16.f16.f32 "
                        "{%0,%1,%2,%3}, {%4,%5,%6,%7}, {%8,%9}, {%0,%1,%2,%3};"
                        : "+f"(acc[mi][ni][0]), "+f"(acc[mi][ni][1]),
                          "+f"(acc[mi][ni][2]), "+f"(acc[mi][ni][3])
                        : "r"(a[mi][0]), "r"(a[mi][1]), "r"(a[mi][2]), "r"(a[mi][3]),
                          "r"(bf[ni][0]), "r"(bf[ni][1]));
        }
        __syncthreads();
    }

    // epilogue: + b1[c] + x residual, float2 stores
    const int bb  = (int)(p0 >> 14);
    const int hw0 = (int)(p0 & 16383) + wn * 32 + (lane & 3) * 2;
    #pragma unroll
    for (int mi = 0; mi < 4; mi++) {
        int cb = mt * 128 + wm * 64 + mi * 16 + (lane >> 2);
        #pragma unroll
        for (int h = 0; h < 2; h++) {
            int c = cb + h * 8;
            float bias = __ldg(b1 + c);
            size_t base = ((size_t)(bb * Cc + c)) * HW + hw0;
            #pragma unroll
            for (int ni = 0; ni < 4; ni++) {
                size_t o = base + ni * 8;
                float2 xv = *(const float2*)(x + o);
                float2 r;
                r.x = acc[mi][ni][h * 2 + 0] + bias + xv.x;
                r.y = acc[mi][ni][h * 2 + 1] + bias + xv.y;
                *(float2*)(out + o) = r;
            }
        }
    }
}

// ---------------------------------------------------------------------------
extern "C" void kernel_launch(void* const* d_in, const int* in_sizes, int n_in,
                              void* d_out, int out_size) {
    const float* x     = (const float*)d_in[0];
    const float* gamma = (const float*)d_in[1];
    const float* beta  = (const float*)d_in[2];
    const float* lbp   = (const float*)d_in[3];
    const float* w1    = (const float*)d_in[4];
    const float* b1    = (const float*)d_in[5];
    float* out = (float*)d_out;

    static bool attr_done = false;
    if (!attr_done) {
        cudaFuncSetAttribute(gemm_kernel,
                             cudaFuncAttributeMaxDynamicSharedMemorySize,
                             2 * STG_BYTES);
        attr_done = true;
    }

    stats_part<<<dim3(Cc, Bn), 256>>>(x);
    finalize_stats<<<1, Cc>>>(gamma, beta);
    w1half<<<(Cc * NWw) / 256, 256>>>(w1);
    dw_kernel<<<dim3(32, 16, Bn), 256>>>(x, lbp);
    gemm_kernel<<<dim3(2, NPIX / 128), 256, 2 * STG_BYTES>>>(x, b1, out);
}